// round 9
// baseline (speedup 1.0000x reference)
#include <cuda_runtime.h>
#include <cstring>

#define BB 128
#define TT 512
#define II 128
#define HH 256

__device__ float g_xp[(size_t)BB * TT * HH];   // [B][T][H] fp32 scratch (fits L2)

// Packed fp32x2 FMA (sm_103a).
__device__ __forceinline__ float2 ffma2(float2 a, float2 b, float2 c) {
    unsigned long long ua, ub, uc, ud;
    memcpy(&ua, &a, 8); memcpy(&ub, &b, 8); memcpy(&uc, &c, 8);
    asm("fma.rn.f32x2 %0, %1, %2, %3;" : "=l"(ud) : "l"(ua), "l"(ub), "l"(uc));
    float2 d; memcpy(&d, &ud, 8); return d;
}

// Safe fast tanh: e = exp(-2|x|) in (0,1] -> no overflow; validated rel_err 6e-8.
__device__ __forceinline__ float fast_tanh(float x) {
    float e = __expf(-2.0f * fabsf(x));
    float r = __fdividef(1.0f - e, 1.0f + e);
    return copysignf(r, x);
}

// ---------------------------------------------------------------------------
// Phase 1: xp[r,h] = x[r,:] . W_ih[h,:] + (b_ih[h] + b_hh[h])
// 128 CTAs x 256 threads; W_ih row per thread in regs; x double-buffered.
// ---------------------------------------------------------------------------
__global__ void __launch_bounds__(256, 1)
rnn_xproj(const float* __restrict__ x,
          const float* __restrict__ W_ih,
          const float* __restrict__ b_ih,
          const float* __restrict__ b_hh) {
    __shared__ float xs[2][8 * II];

    const int h = threadIdx.x;

    const float4* Wi4 = (const float4*)W_ih;
    float4 wreg[32];
#pragma unroll
    for (int q = 0; q < 32; q++) wreg[q] = Wi4[h * 32 + q];

    const float bias = b_ih[h] + b_hh[h];
    const size_t base_row = (size_t)blockIdx.x * 512;

    ((float4*)xs[0])[h] = ((const float4*)(x + base_row * II))[h];
    __syncthreads();

    for (int tile = 0; tile < 64; tile++) {
        const int cur = tile & 1;
        if (tile < 63) {
            ((float4*)xs[cur ^ 1])[h] =
                ((const float4*)(x + (base_row + (size_t)(tile + 1) * 8) * II))[h];
        }

        const size_t r0 = base_row + (size_t)tile * 8;
#pragma unroll
        for (int r = 0; r < 8; r += 2) {
            const float4* x0 = (const float4*)(xs[cur] + r * II);
            const float4* x1 = (const float4*)(xs[cur] + (r + 1) * II);
            float2 a0 = make_float2(bias, 0.0f), a1 = make_float2(0.0f, 0.0f);
            float2 c0 = make_float2(bias, 0.0f), c1 = make_float2(0.0f, 0.0f);
#pragma unroll
            for (int q = 0; q < 32; q++) {
                float4 xv = x0[q], yv = x1[q];
                float2 wlo = make_float2(wreg[q].x, wreg[q].y);
                float2 whi = make_float2(wreg[q].z, wreg[q].w);
                a0 = ffma2(make_float2(xv.x, xv.y), wlo, a0);
                a1 = ffma2(make_float2(xv.z, xv.w), whi, a1);
                c0 = ffma2(make_float2(yv.x, yv.y), wlo, c0);
                c1 = ffma2(make_float2(yv.z, yv.w), whi, c1);
            }
            g_xp[(r0 + r) * HH + h]     = (a0.x + a0.y) + (a1.x + a1.y);
            g_xp[(r0 + r + 1) * HH + h] = (c0.x + c0.y) + (c1.x + c1.y);
        }
        __syncthreads();
    }
}

// ---------------------------------------------------------------------------
// Phase 2 + 3: recurrent scan. 128 CTAs x 512 threads (16 warps).
// K-QUARTER LAYOUT, 2 features/thread:
//   warp w, lane l: slot f = l>>2 (0..7), quarter kq = l&3.
//   Thread handles features jA = w*16+f and jB = jA+8, over interleaved
//   h/W float4 indices {4*qq + kq}, qq = 0..15.
//   - every h LDS.128: 4 addresses X..X+48, one 128B segment -> 1 wf;
//     16 loads/thread, each feeding BOTH features -> h-wf halves vs R8.
//   - W: qq<11 in regs (2x11 f4 = 88 regs); qq=11..15 in SMEM [s][tid]
//     (warp reads 512B consecutive -> 4 wf).
//   - reduction: shfl.xor 1 & 2 over the kq lanes; kq==0 lanes load xp,
//     tanh, publish. ONE __syncthreads per step.
// ---------------------------------------------------------------------------
#define NREGQ 11          // reg f4 per feature (qq 0..10)
#define NTAILQ 5          // SMEM f4 per feature (qq 11..15)

__global__ void __launch_bounds__(512, 1)
rnn_scan(const float* __restrict__ W_hh,
         const float* __restrict__ W_fc,
         const float* __restrict__ b_fc,
         float* __restrict__ out) {
    extern __shared__ float sm[];
    float4* wt4 = (float4*)sm;                    // [2*NTAILQ][512] f4 = 80 KB
    float*  hA  = sm + 2 * NTAILQ * 512 * 4;      // 256
    float*  hB  = hA + HH;                        // 256
    float*  red = hB + HH;                        // 8

    const int tid  = threadIdx.x;
    const int lane = tid & 31;
    const int w    = tid >> 5;
    const int f    = lane >> 2;                   // 0..7
    const int kq   = lane & 3;                    // 0..3
    const int jA   = (w << 4) | f;                // 0..255
    const int jB   = jA + 8;
    const int b    = blockIdx.x;

    const float4* W4 = (const float4*)W_hh;       // row j = W4[j*64 .. +63]

    float4 wregA[NREGQ], wregB[NREGQ];
#pragma unroll
    for (int qq = 0; qq < NREGQ; qq++) {
        wregA[qq] = W4[jA * 64 + 4 * qq + kq];
        wregB[qq] = W4[jB * 64 + 4 * qq + kq];
    }
#pragma unroll
    for (int s = 0; s < NTAILQ; s++) {
        wt4[s * 512 + tid]                 = W4[jA * 64 + 4 * (NREGQ + s) + kq];
        wt4[(NTAILQ + s) * 512 + tid]      = W4[jB * 64 + 4 * (NREGQ + s) + kq];
    }

    if (tid < HH) { hA[tid] = 0.0f; hB[tid] = 0.0f; }
    __syncthreads();

    const float*  xpA = g_xp + (size_t)b * TT * HH + jA;
    const float*  xpB = g_xp + (size_t)b * TT * HH + jB;
    const float4* wtp = wt4 + tid;                // wtp[s*512]

    float* hcur = hA;
    float* hnxt = hB;

    for (int t = 0; t < TT; t++) {
        float xvA = 0.0f, xvB = 0.0f;
        if (kq == 0) {                            // only publishers need xp
            xvA = xpA[(size_t)t * HH];            // L2-hit, consumed late
            xvB = xpB[(size_t)t * HH];
        }

        const float4* hs4 = (const float4*)hcur;
        float2 aA0 = make_float2(0.0f, 0.0f), aA1 = aA0;
        float2 aB0 = aA0, aB1 = aA0;

        // SMEM W-tail first: LDS latency overlaps the register-W FMA stream
#pragma unroll
        for (int s = 0; s < NTAILQ; s++) {
            float4 h4 = hs4[4 * (NREGQ + s) + kq];
            float4 wA = wtp[s * 512];
            float4 wB = wtp[(NTAILQ + s) * 512];
            aA0 = ffma2(make_float2(h4.x, h4.y), make_float2(wA.x, wA.y), aA0);
            aA1 = ffma2(make_float2(h4.z, h4.w), make_float2(wA.z, wA.w), aA1);
            aB0 = ffma2(make_float2(h4.x, h4.y), make_float2(wB.x, wB.y), aB0);
            aB1 = ffma2(make_float2(h4.z, h4.w), make_float2(wB.z, wB.w), aB1);
        }
#pragma unroll
        for (int qq = 0; qq < NREGQ; qq++) {
            float4 h4 = hs4[4 * qq + kq];
            aA0 = ffma2(make_float2(h4.x, h4.y), make_float2(wregA[qq].x, wregA[qq].y), aA0);
            aA1 = ffma2(make_float2(h4.z, h4.w), make_float2(wregA[qq].z, wregA[qq].w), aA1);
            aB0 = ffma2(make_float2(h4.x, h4.y), make_float2(wregB[qq].x, wregB[qq].y), aB0);
            aB1 = ffma2(make_float2(h4.z, h4.w), make_float2(wregB[qq].z, wregB[qq].w), aB1);
        }

        float dotA = (aA0.x + aA0.y) + (aA1.x + aA1.y);
        float dotB = (aB0.x + aB0.y) + (aB1.x + aB1.y);

        // reduce over the 4 kq lanes (lane bits 0-1)
        dotA += __shfl_xor_sync(0xffffffffu, dotA, 1);
        dotB += __shfl_xor_sync(0xffffffffu, dotB, 1);
        dotA += __shfl_xor_sync(0xffffffffu, dotA, 2);
        dotB += __shfl_xor_sync(0xffffffffu, dotB, 2);

        if (kq == 0) {
            hnxt[jA] = fast_tanh(xvA + dotA);
            hnxt[jB] = fast_tanh(xvB + dotB);
        }
        __syncthreads();                          // single barrier: h published

        float* tmp = hcur; hcur = hnxt; hnxt = tmp;
    }

    // Phase 3: out[b] = sigmoid(h . W_fc + b_fc)  (first 256 threads)
    if (tid < HH) {
        float v = hcur[tid] * W_fc[tid];
#pragma unroll
        for (int o = 16; o > 0; o >>= 1) v += __shfl_down_sync(0xffffffffu, v, o);
        if ((tid & 31) == 0) red[tid >> 5] = v;
    }
    __syncthreads();
    if (tid == 0) {
        float s = b_fc[0];
#pragma unroll
        for (int w2 = 0; w2 < 8; w2++) s += red[w2];
        out[b] = 1.0f / (1.0f + expf(-s));
    }
}

// ---------------------------------------------------------------------------

extern "C" void kernel_launch(void* const* d_in, const int* in_sizes, int n_in,
                              void* d_out, int out_size) {
    const float* x    = (const float*)d_in[0];
    const float* W_ih = (const float*)d_in[1];
    const float* W_hh = (const float*)d_in[2];
    const float* b_ih = (const float*)d_in[3];
    const float* b_hh = (const float*)d_in[4];
    const float* W_fc = (const float*)d_in[5];
    const float* b_fc = (const float*)d_in[6];
    float* out = (float*)d_out;

    const int smem_b = (2 * NTAILQ * 512 * 4 + 2 * HH + 8) * (int)sizeof(float); // ~84 KB
    cudaFuncSetAttribute(rnn_scan, cudaFuncAttributeMaxDynamicSharedMemorySize, smem_b);

    rnn_xproj<<<128, 256>>>(x, W_ih, b_ih, b_hh);
    rnn_scan<<<BB, 512, smem_b>>>(W_hh, W_fc, b_fc, out);
}